// round 7
// baseline (speedup 1.0000x reference)
#include <cuda_runtime.h>

#define BATCH 4096
#define SEQ   200
#define EMB   128
#define VOCAB 100000

// Scratch: P[v] = { emb[v]·W0, emb[v]·W1 }  (recomputed every launch)
__device__ __align__(16) float Pbuf[VOCAB * 2];

// ---------------- Kernel 1: P = embeddings @ W^T  (warp per vocab row) ----------------
__global__ __launch_bounds__(128)
void precompute_kernel(const float* __restrict__ emb,
                       const float* __restrict__ W)
{
    const int warp_g = (blockIdx.x * blockDim.x + threadIdx.x) >> 5;  // vocab row
    const int lane   = threadIdx.x & 31;
    if (warp_g >= VOCAB) return;

    // 512B coalesced row load: one float4 per lane.
    float4 e  = __ldg(&reinterpret_cast<const float4*>(emb + warp_g * EMB)[lane]);
    float4 w0 = __ldg(&reinterpret_cast<const float4*>(W)[lane]);
    float4 w1 = __ldg(&reinterpret_cast<const float4*>(W + EMB)[lane]);

    float d0 = e.x * w0.x + e.y * w0.y + e.z * w0.z + e.w * w0.w;
    float d1 = e.x * w1.x + e.y * w1.y + e.z * w1.z + e.w * w1.w;

    #pragma unroll
    for (int off = 16; off > 0; off >>= 1) {
        d0 += __shfl_xor_sync(0xFFFFFFFFu, d0, off);
        d1 += __shfl_xor_sync(0xFFFFFFFFu, d1, off);
    }
    if (lane == 0)
        reinterpret_cast<float2*>(Pbuf)[warp_g] = make_float2(d0, d1);
}

// ---------------- Kernel 2: masked mean over P + bias  (warp per batch row) ----------------
__global__ __launch_bounds__(128)
void pool_kernel(const int* __restrict__ x,
                 const float* __restrict__ bias,
                 float* __restrict__ out)
{
    const int row  = (blockIdx.x * blockDim.x + threadIdx.x) >> 5;
    const int lane = threadIdx.x & 31;
    if (row >= BATCH) return;

    const int* xr = x + row * SEQ;
    const float2* P = reinterpret_cast<const float2*>(Pbuf);

    float a0 = 0.f, a1 = 0.f, c = 0.f;

    // 6 full strided iterations (lane+160 <= 191 < 200), then tail.
    #pragma unroll
    for (int i = 0; i < 6; i++) {
        int idx = xr[lane + 32 * i];          // coalesced 128B index load
        if (idx >= 0) {
            float2 p = __ldg(&P[idx]);        // 8B gather (L2/L1-resident table)
            a0 += p.x; a1 += p.y; c += 1.f;
        }
    }
    if (lane + 192 < SEQ) {                   // lanes 0..7
        int idx = xr[lane + 192];
        if (idx >= 0) {
            float2 p = __ldg(&P[idx]);
            a0 += p.x; a1 += p.y; c += 1.f;
        }
    }

    #pragma unroll
    for (int off = 16; off > 0; off >>= 1) {
        a0 += __shfl_xor_sync(0xFFFFFFFFu, a0, off);
        a1 += __shfl_xor_sync(0xFFFFFFFFu, a1, off);
        c  += __shfl_xor_sync(0xFFFFFFFFu, c,  off);
    }
    if (lane == 0) {
        float inv = 1.0f / c;                 // c >= 1 (column 0 always valid)
        out[row * 2 + 0] = a0 * inv + bias[0];
        out[row * 2 + 1] = a1 * inv + bias[1];
    }
}

extern "C" void kernel_launch(void* const* d_in, const int* in_sizes, int n_in,
                              void* d_out, int out_size)
{
    const int* x     = (const int*)d_in[0];       // int32 [4096,200]
    const float* emb = (const float*)d_in[1];     // [100000,128]
    const float* W   = (const float*)d_in[2];     // [2,128]
    const float* b   = (const float*)d_in[3];     // [2]
    float* out       = (float*)d_out;             // [4096,2]

    // K1: 4 vocab rows per 128-thread block.
    precompute_kernel<<<(VOCAB + 3) / 4, 128>>>(emb, W);
    // K2: 4 batch rows per 128-thread block (same stream -> ordered).
    pool_kernel<<<(BATCH + 3) / 4, 128>>>(x, b, out);
}

// round 8
// speedup vs baseline: 1.3907x; 1.3907x over previous
#include <cuda_runtime.h>

#define BATCH 4096
#define SEQ   200
#define EMB   128
#define VOCAB 100000
#define RPW   8                       // vocab rows per warp in precompute

// Scratch: P[v] = { emb[v]·W0, emb[v]·W1 }  (recomputed every launch)
__device__ __align__(16) float Pbuf[VOCAB * 2];

// ---------------- Kernel 1: P = embeddings @ W^T  (8 rows per warp, pipelined) ----------
__global__ __launch_bounds__(256)
void precompute_kernel(const float* __restrict__ emb,
                       const float* __restrict__ W)
{
    const int warp_g = (blockIdx.x * blockDim.x + threadIdx.x) >> 5;
    const int lane   = threadIdx.x & 31;
    const int row0   = warp_g * RPW;
    if (row0 >= VOCAB) return;        // VOCAB=100000 = 12500*8, grid divides exactly

    float4 w0 = __ldg(&reinterpret_cast<const float4*>(W)[lane]);
    float4 w1 = __ldg(&reinterpret_cast<const float4*>(W + EMB)[lane]);

    // 8 independent coalesced 512B row loads -> MLP=8.
    float4 e[RPW];
    #pragma unroll
    for (int i = 0; i < RPW; i++)
        e[i] = __ldg(&reinterpret_cast<const float4*>(emb + (row0 + i) * EMB)[lane]);

    float d0[RPW], d1[RPW];
    #pragma unroll
    for (int i = 0; i < RPW; i++) {
        d0[i] = e[i].x * w0.x + e[i].y * w0.y + e[i].z * w0.z + e[i].w * w0.w;
        d1[i] = e[i].x * w1.x + e[i].y * w1.y + e[i].z * w1.z + e[i].w * w1.w;
    }

    // 16 independent shuffle-reduce chains -> pipelined through SHFL unit.
    #pragma unroll
    for (int off = 16; off > 0; off >>= 1) {
        #pragma unroll
        for (int i = 0; i < RPW; i++) {
            d0[i] += __shfl_xor_sync(0xFFFFFFFFu, d0[i], off);
            d1[i] += __shfl_xor_sync(0xFFFFFFFFu, d1[i], off);
        }
    }

    if (lane == 0) {
        float2* Pr = reinterpret_cast<float2*>(Pbuf) + row0;
        #pragma unroll
        for (int i = 0; i < RPW; i++)
            Pr[i] = make_float2(d0[i], d1[i]);   // 64B contiguous from lane 0
    }
}

// ---------------- Kernel 2: masked mean over P + bias  (warp per batch row) -------------
__global__ __launch_bounds__(256)
void pool_kernel(const int* __restrict__ x,
                 const float* __restrict__ bias,
                 float* __restrict__ out)
{
    const int row  = (blockIdx.x * blockDim.x + threadIdx.x) >> 5;
    const int lane = threadIdx.x & 31;
    if (row >= BATCH) return;

    const int* xr = x + row * SEQ;
    const float2* P = reinterpret_cast<const float2*>(Pbuf);

    // Branchless: load indices first (7 coalesced loads), then 7 batched gathers.
    int   idxv[7];
    #pragma unroll
    for (int i = 0; i < 6; i++) idxv[i] = xr[lane + 32 * i];
    idxv[6] = (lane + 192 < SEQ) ? xr[lane + 192] : -1;

    float a0 = 0.f, a1 = 0.f, c = 0.f;
    #pragma unroll
    for (int i = 0; i < 7; i++) {
        int   idx = idxv[i];
        float m   = (idx >= 0) ? 1.f : 0.f;
        int   ci  = (idx >= 0) ? idx : 0;      // padding -> row 0 (broadcast, L1-hit, 8B)
        float2 p  = __ldg(&P[ci]);
        a0 = fmaf(m, p.x, a0);
        a1 = fmaf(m, p.y, a1);
        c += m;
    }

    #pragma unroll
    for (int off = 16; off > 0; off >>= 1) {
        a0 += __shfl_xor_sync(0xFFFFFFFFu, a0, off);
        a1 += __shfl_xor_sync(0xFFFFFFFFu, a1, off);
        c  += __shfl_xor_sync(0xFFFFFFFFu, c,  off);
    }
    if (lane == 0) {
        float inv = 1.0f / c;                  // c >= 1 (column 0 always valid)
        out[row * 2 + 0] = a0 * inv + bias[0];
        out[row * 2 + 1] = a1 * inv + bias[1];
    }
}

extern "C" void kernel_launch(void* const* d_in, const int* in_sizes, int n_in,
                              void* d_out, int out_size)
{
    const int* x     = (const int*)d_in[0];       // int32 [4096,200]
    const float* emb = (const float*)d_in[1];     // [100000,128]
    const float* W   = (const float*)d_in[2];     // [2,128]
    const float* b   = (const float*)d_in[3];     // [2]
    float* out       = (float*)d_out;             // [4096,2]

    // K1: 8 warps/block * 8 rows/warp = 64 rows per block.
    precompute_kernel<<<(VOCAB + 63) / 64, 256>>>(emb, W);
    // K2: 8 batch rows per 256-thread block (same stream -> ordered after K1).
    pool_kernel<<<(BATCH + 7) / 8, 256>>>(x, b, out);
}

// round 9
// speedup vs baseline: 1.6416x; 1.1805x over previous
#include <cuda_runtime.h>

#define BATCH 4096
#define SEQ   200
#define EMB   128
#define VOCAB 100000

// Scratch: P[v] = { emb[v]·W0, emb[v]·W1 }  (recomputed every launch)
__device__ __align__(16) float Pbuf[VOCAB * 2];

// ---- Kernel 1: P = embeddings @ W^T.  8 lanes per row, 8 rows per warp. ----
// Lane l: sub = l&7 (quarter of row), grp = l>>3 (row within group of 4).
// One LDG.128 warp instr covers 4 full rows (4 x 128B lines, fully coalesced).
__global__ __launch_bounds__(256)
void precompute_kernel(const float* __restrict__ emb,
                       const float* __restrict__ W)
{
    const int warp_g = (blockIdx.x * blockDim.x + threadIdx.x) >> 5;
    const int lane   = threadIdx.x & 31;
    const int sub    = lane & 7;
    const int grp    = lane >> 3;

    const int row_base = warp_g * 8;
    if (row_base >= VOCAB) return;

    const float4* emb4 = reinterpret_cast<const float4*>(emb);
    const float4* W4   = reinterpret_cast<const float4*>(W);

    // Weight quarters this lane needs (L1-resident broadcasts).
    float4 w0[4], w1[4];
    #pragma unroll
    for (int i = 0; i < 4; i++) {
        w0[i] = __ldg(&W4[sub + 8 * i]);
        w1[i] = __ldg(&W4[32 + sub + 8 * i]);
    }

    int rA = row_base + grp;            // group A row
    int rB = row_base + 4 + grp;        // group B row
    int cA = (rA < VOCAB) ? rA : VOCAB - 1;   // clamp for tail block loads
    int cB = (rB < VOCAB) ? rB : VOCAB - 1;

    // 8 independent coalesced loads (MLP=8).
    float4 eA[4], eB[4];
    #pragma unroll
    for (int i = 0; i < 4; i++) {
        eA[i] = __ldg(&emb4[cA * 32 + sub + 8 * i]);
        eB[i] = __ldg(&emb4[cB * 32 + sub + 8 * i]);
    }

    float dA0 = 0.f, dA1 = 0.f, dB0 = 0.f, dB1 = 0.f;
    #pragma unroll
    for (int i = 0; i < 4; i++) {
        dA0 += eA[i].x * w0[i].x + eA[i].y * w0[i].y + eA[i].z * w0[i].z + eA[i].w * w0[i].w;
        dA1 += eA[i].x * w1[i].x + eA[i].y * w1[i].y + eA[i].z * w1[i].z + eA[i].w * w1[i].w;
        dB0 += eB[i].x * w0[i].x + eB[i].y * w0[i].y + eB[i].z * w0[i].z + eB[i].w * w0[i].w;
        dB1 += eB[i].x * w1[i].x + eB[i].y * w1[i].y + eB[i].z * w1[i].z + eB[i].w * w1[i].w;
    }

    // 3-level butterfly within each 8-lane group (12 SHFL total for 8 rows).
    #pragma unroll
    for (int off = 4; off > 0; off >>= 1) {
        dA0 += __shfl_xor_sync(0xFFFFFFFFu, dA0, off);
        dA1 += __shfl_xor_sync(0xFFFFFFFFu, dA1, off);
        dB0 += __shfl_xor_sync(0xFFFFFFFFu, dB0, off);
        dB1 += __shfl_xor_sync(0xFFFFFFFFu, dB1, off);
    }

    if (sub == 0) {
        float2* P2 = reinterpret_cast<float2*>(Pbuf);
        if (rA < VOCAB) P2[rA] = make_float2(dA0, dA1);
        if (rB < VOCAB) P2[rB] = make_float2(dB0, dB1);
    }
}

// ---- Kernel 2: masked mean over P + bias.  2 warps per batch row. ----
__global__ __launch_bounds__(256)
void pool_kernel(const int* __restrict__ x,
                 const float* __restrict__ bias,
                 float* __restrict__ out)
{
    const int tid     = threadIdx.x;
    const int warp    = tid >> 5;          // 0..7 in block
    const int lane    = tid & 31;
    const int warp_g  = blockIdx.x * 8 + warp;
    const int row     = warp_g >> 1;       // 4 rows per block
    const int half    = warp_g & 1;
    if (row >= BATCH) return;

    const int* xr = x + row * SEQ + half * 100;
    const float2* P = reinterpret_cast<const float2*>(Pbuf);

    // 100 tokens per warp: 3 full strided index loads + 4-lane tail.
    int idxv[4];
    #pragma unroll
    for (int i = 0; i < 3; i++) idxv[i] = xr[lane + 32 * i];
    idxv[3] = (lane < 4) ? xr[96 + lane] : -1;

    float a0 = 0.f, a1 = 0.f, c = 0.f;
    #pragma unroll
    for (int i = 0; i < 4; i++) {
        int   idx = idxv[i];
        float m   = (idx >= 0) ? 1.f : 0.f;
        int   ci  = (idx >= 0) ? idx : 0;      // padding -> row 0 (broadcast 8B, L1-hit)
        float2 p  = __ldg(&P[ci]);
        a0 = fmaf(m, p.x, a0);
        a1 = fmaf(m, p.y, a1);
        c += m;
    }

    #pragma unroll
    for (int off = 16; off > 0; off >>= 1) {
        a0 += __shfl_xor_sync(0xFFFFFFFFu, a0, off);
        a1 += __shfl_xor_sync(0xFFFFFFFFu, a1, off);
        c  += __shfl_xor_sync(0xFFFFFFFFu, c,  off);
    }

    __shared__ __align__(16) float4 part[8];
    if (lane == 0) part[warp] = make_float4(a0, a1, c, 0.f);
    __syncthreads();

    // 4 rows per block: thread t < 4 combines halves of row (blockIdx.x*4 + t).
    if (tid < 4) {
        float4 h0 = part[2 * tid];
        float4 h1 = part[2 * tid + 1];
        float s0 = h0.x + h1.x;
        float s1 = h0.y + h1.y;
        float cn = h0.z + h1.z;                 // >= 1 (column 0 always valid)
        float inv = 1.0f / cn;
        int r = blockIdx.x * 4 + tid;
        out[r * 2 + 0] = s0 * inv + bias[0];
        out[r * 2 + 1] = s1 * inv + bias[1];
    }
}

extern "C" void kernel_launch(void* const* d_in, const int* in_sizes, int n_in,
                              void* d_out, int out_size)
{
    const int* x     = (const int*)d_in[0];       // int32 [4096,200]
    const float* emb = (const float*)d_in[1];     // [100000,128]
    const float* W   = (const float*)d_in[2];     // [2,128]
    const float* b   = (const float*)d_in[3];     // [2]
    float* out       = (float*)d_out;             // [4096,2]

    // K1: 8 warps/block x 8 rows/warp = 64 rows/block.
    precompute_kernel<<<(VOCAB + 63) / 64, 256>>>(emb, W);
    // K2: 8 warps/block = 4 rows/block -> 1024 blocks (same stream, ordered).
    pool_kernel<<<BATCH / 4, 256>>>(x, b, out);
}